// round 12
// baseline (speedup 1.0000x reference)
#include <cuda_runtime.h>
#include <cuda_bf16.h>
#include <cstdint>

#define S_LEN 2048
#define B_SZ  64
#define I_DIM 128
#define H_DIM 256
#define O_DIM 64
#define NROWS (S_LEN * B_SZ)   // 131072 rows, n = b*S + s

// Scratch (static device arrays: allocation-free rule).
__device__ float g_bufA[(size_t)NROWS * H_DIM];
__device__ float g_bufB[(size_t)NROWS * H_DIM];
__device__ float g_bufC[(size_t)NROWS * H_DIM];
__device__ float g_bufD[(size_t)NROWS * H_DIM];
// Head-fusion scratch
__device__ float g_M[H_DIM * H_DIM];     // fc2W @ fc1W
__device__ float g_hW[O_DIM * H_DIM];    // fc3W @ g_M
__device__ float g_hb[O_DIM];            // fused bias

// ---- packed fp32x2 helpers (sm_100+) --------------------------------------
__device__ __forceinline__ void fma2(unsigned long long& d,
                                     unsigned long long a,
                                     unsigned long long b)
{
    asm("fma.rn.f32x2 %0, %1, %2, %0;" : "+l"(d) : "l"(a), "l"(b));
}
__device__ __forceinline__ unsigned long long add2(unsigned long long a,
                                                   unsigned long long b)
{
    unsigned long long r;
    asm("add.rn.f32x2 %0, %1, %2;" : "=l"(r) : "l"(a), "l"(b));
    return r;
}
__device__ __forceinline__ unsigned long long splat2(float x)
{
    unsigned long long r;
    asm("mov.b64 %0, {%1, %1};" : "=l"(r) : "f"(x));
    return r;
}
__device__ __forceinline__ float2 unpack2(unsigned long long v)
{
    float2 r;
    asm("mov.b64 {%0, %1}, %2;" : "=f"(r.x), "=f"(r.y) : "l"(v));
    return r;
}
// Branchless fast tanh: 1 - 2/(exp(2x)+1). Saturates correctly at +-1.
__device__ __forceinline__ float fast_tanh(float x)
{
    float e = __expf(2.f * x);
    return 1.f - __fdividef(2.f, e + 1.f);
}
// mbarrier parity wait (acquire.cluster: orders peer st.async data)
__device__ __forceinline__ void mbar_wait(uint32_t addr, uint32_t parity)
{
    uint32_t done;
    asm volatile(
        "{\n\t.reg .pred p;\n\t"
        "mbarrier.try_wait.parity.acquire.cluster.shared::cta.b64 p, [%1], %2;\n\t"
        "selp.b32 %0, 1, 0, p;\n\t}"
        : "=r"(done) : "r"(addr), "r"(parity) : "memory");
    if (!done) {
        asm volatile(
            "{\n\t.reg .pred P1;\n\t"
            "WL_%=:\n\t"
            "mbarrier.try_wait.parity.acquire.cluster.shared::cta.b64 P1, [%0], %1, 0x989680;\n\t"
            "@P1 bra.uni WD_%=;\n\t"
            "bra.uni WL_%=;\n\t"
            "WD_%=:\n\t}"
            :: "r"(addr), "r"(parity) : "memory");
    }
}

// ---------------------------------------------------------------------------
// GEMM: C[M,N] = A[M,K] @ W[N,K]^T + b1[n] (+ b2[n])
// BM=128, BN=128, BK=16, TM=TN=8, 256 threads. fp32x2 packed accumulation.
// (At the fp32 issue roofline per R7-R10 profiles -- frozen.)
// ---------------------------------------------------------------------------
__global__ __launch_bounds__(256, 2) void sgemm_bias(
    const float* __restrict__ A, const float* __restrict__ W,
    const float* __restrict__ b1, const float* __restrict__ b2,
    float* __restrict__ C, int M, int N, int K)
{
    constexpr int BM = 128, BN = 128, BK = 16, TM = 8, TN = 8;
    __shared__ __align__(16) float As[BK][BM + 4];
    __shared__ __align__(16) float Ws[BK][BN + 4];

    const int tid = threadIdx.x;
    const int tx  = tid & 15;   // n sub-tile
    const int ty  = tid >> 4;   // m sub-tile
    const int m0  = blockIdx.y * BM;
    const int n0  = blockIdx.x * BN;

    unsigned long long acc2[TM / 2][TN];
#pragma unroll
    for (int p = 0; p < TM / 2; p++)
#pragma unroll
        for (int j = 0; j < TN; j++) acc2[p][j] = 0ULL;

    for (int k0 = 0; k0 < K; k0 += BK) {
#pragma unroll
        for (int l = 0; l < 2; l++) {
            int idx = tid + l * 256;
            int r = idx >> 2;
            int c = (idx & 3) << 2;
            float4 v = *reinterpret_cast<const float4*>(
                A + (size_t)(m0 + r) * K + k0 + c);
            As[c + 0][r] = v.x; As[c + 1][r] = v.y;
            As[c + 2][r] = v.z; As[c + 3][r] = v.w;
        }
#pragma unroll
        for (int l = 0; l < 2; l++) {
            int idx = tid + l * 256;
            int r = idx >> 2;
            int c = (idx & 3) << 2;
            float4 v = make_float4(0.f, 0.f, 0.f, 0.f);
            if (n0 + r < N)
                v = *reinterpret_cast<const float4*>(
                    W + (size_t)(n0 + r) * K + k0 + c);
            Ws[c + 0][r] = v.x; Ws[c + 1][r] = v.y;
            Ws[c + 2][r] = v.z; Ws[c + 3][r] = v.w;
        }
        __syncthreads();

#pragma unroll
        for (int k = 0; k < BK; k++) {
            ulonglong2 ra = *reinterpret_cast<const ulonglong2*>(&As[k][ty * TM]);
            ulonglong2 rb = *reinterpret_cast<const ulonglong2*>(&As[k][ty * TM + 4]);
            unsigned long long rm2[4] = { ra.x, ra.y, rb.x, rb.y };

            float4 n0v = *reinterpret_cast<const float4*>(&Ws[k][tx * TN]);
            float4 n1v = *reinterpret_cast<const float4*>(&Ws[k][tx * TN + 4]);
            unsigned long long rn2[TN];
            rn2[0] = splat2(n0v.x); rn2[1] = splat2(n0v.y);
            rn2[2] = splat2(n0v.z); rn2[3] = splat2(n0v.w);
            rn2[4] = splat2(n1v.x); rn2[5] = splat2(n1v.y);
            rn2[6] = splat2(n1v.z); rn2[7] = splat2(n1v.w);

#pragma unroll
            for (int p = 0; p < TM / 2; p++)
#pragma unroll
                for (int j = 0; j < TN; j++)
                    fma2(acc2[p][j], rm2[p], rn2[j]);
        }
        __syncthreads();
    }

    const int gn0 = n0 + tx * TN;
    if (gn0 < N) {
        float bias[TN];
#pragma unroll
        for (int j = 0; j < TN; j++) {
            int gn = gn0 + j;
            bias[j] = b1[gn] + (b2 ? b2[gn] : 0.f);
        }
#pragma unroll
        for (int p = 0; p < TM / 2; p++) {
            float r0[TN], r1[TN];
#pragma unroll
            for (int j = 0; j < TN; j++) {
                float2 u = unpack2(acc2[p][j]);
                r0[j] = u.x + bias[j];
                r1[j] = u.y + bias[j];
            }
            int gm = m0 + ty * TM + 2 * p;
            float4 o;
            o = make_float4(r0[0], r0[1], r0[2], r0[3]);
            *reinterpret_cast<float4*>(C + (size_t)gm * N + gn0) = o;
            o = make_float4(r0[4], r0[5], r0[6], r0[7]);
            *reinterpret_cast<float4*>(C + (size_t)gm * N + gn0 + 4) = o;
            o = make_float4(r1[0], r1[1], r1[2], r1[3]);
            *reinterpret_cast<float4*>(C + (size_t)(gm + 1) * N + gn0) = o;
            o = make_float4(r1[4], r1[5], r1[6], r1[7]);
            *reinterpret_cast<float4*>(C + (size_t)(gm + 1) * N + gn0 + 4) = o;
        }
    }
}

// ---------------------------------------------------------------------------
// Small NN matmul for head fusion: C[i,j] = sum_k A[i,k] * B[k,j]
// ---------------------------------------------------------------------------
__global__ __launch_bounds__(256) void matmul_nn(
    const float* __restrict__ A, const float* __restrict__ B,
    float* __restrict__ C)
{
    __shared__ float arow[H_DIM];
    const int i = blockIdx.x, j = threadIdx.x;
    arow[j] = A[i * H_DIM + j];
    __syncthreads();
    float s = 0.f;
#pragma unroll 8
    for (int k = 0; k < H_DIM; k++)
        s = fmaf(arow[k], B[(size_t)k * H_DIM + j], s);
    C[i * H_DIM + j] = s;
}

// Fused head bias: b' = F3 @ (F2 @ b1 + b2) + b3. One block, 256 threads.
__global__ __launch_bounds__(256) void head_bias(
    const float* __restrict__ F2, const float* __restrict__ b1,
    const float* __restrict__ b2, const float* __restrict__ F3,
    const float* __restrict__ b3, float* __restrict__ bout)
{
    __shared__ float bt[H_DIM];
    const int t = threadIdx.x;
    float s = b2[t];
    for (int k = 0; k < H_DIM; k++)
        s = fmaf(F2[(size_t)t * H_DIM + k], b1[k], s);
    bt[t] = s;
    __syncthreads();
    if (t < O_DIM) {
        float s2 = b3[t];
        for (int k = 0; k < H_DIM; k++)
            s2 = fmaf(F3[(size_t)t * H_DIM + k], bt[k], s2);
        bout[t] = s2;
    }
}

// ---------------------------------------------------------------------------
// Recurrent scan, ZERO intra-CTA barriers.
// H[t] = tanh(Z[t] + W @ H[t-1]); 2-CTA cluster per batch, 512 threads.
// Thread map: warp w owns rows [w*8, w*8+8) of this CTA's half; within a
// warp, lane = kq*8 + ri8 handles row (w*8+ri8) over k in [kq*64, kq*64+64).
//   - h loads: each LDS quarter-phase has a uniform address -> broadcast.
//   - reduction: 2x shfl.bfly (xor 8, xor 16) inside the warp. No staging.
//   - h published to BOTH CTAs via st.async completing each CTA's mbarrier;
//     ONE parity wait per step is the only synchronization.
//   - TRIPLE-buffered h_buf: CTA skew is provably <=1 step, and writes at
//     step s go to buf (s+1)%3 which never collides with a reader at step u
//     for s <= u+1.  (Double buffering would ABA-race without barriers.)
//   - mbar[t&1] ping-pong; tid0 arms phase t+1 after its own phase-t stores
//     and before its phase-t wait; a complete_tx arriving pre-arm just drives
//     the pending tx-count negative (phase still gated on the arrive).
// ---------------------------------------------------------------------------
__global__ void __cluster_dims__(2, 1, 1) __launch_bounds__(512, 1)
scan_rnn(const float* __restrict__ Z, const float* __restrict__ Wr,
         float* __restrict__ Hout)
{
    __shared__ __align__(16) float h_buf[3][H_DIM];
    __shared__ __align__(8) unsigned long long mbar[2];

    const int tid = threadIdx.x;
    uint32_t rank_u;
    asm("mov.u32 %0, %%cluster_ctarank;" : "=r"(rank_u));
    const int rank  = (int)rank_u;
    const int batch = blockIdx.x >> 1;
    const int w    = tid >> 5;       // warp 0..15
    const int lane = tid & 31;
    const int kq   = lane >> 3;      // 0..3  (k-quarter of 64)
    const int ri8  = lane & 7;       // row within warp's 8
    const int lr   = w * 8 + ri8;    // local row 0..127
    const int gr   = rank * 128 + lr;
    const bool fin = (kq == 0);      // finalizer lanes (one per row)

    // W row chunk: row gr, k in [kq*64, kq*64+64): 64 floats = 32 ull,
    // pairs along k matching the packed h loads.
    unsigned long long wp[32];
    {
        const float* wrow = Wr + (size_t)gr * H_DIM + kq * 64;
#pragma unroll
        for (int j = 0; j < 16; j++) {
            ulonglong2 v = *reinterpret_cast<const ulonglong2*>(wrow + j * 4);
            wp[2 * j + 0] = v.x;     // k = 4j, 4j+1
            wp[2 * j + 1] = v.y;     // k = 4j+2, 4j+3
        }
    }

    if (tid < H_DIM) h_buf[0][tid] = 0.f;      // t=0 reads buf 0
    if (tid == 0) {
        uint32_t mb;
        asm("{ .reg .u64 t; cvta.to.shared.u64 t, %1; cvt.u32.u64 %0, t; }"
            : "=r"(mb) : "l"(&mbar[0]));
        asm volatile("mbarrier.init.shared.b64 [%0], 1;" :: "r"(mb) : "memory");
        asm volatile("mbarrier.init.shared.b64 [%0], 1;" :: "r"(mb + 8) : "memory");
    }
    __syncthreads();   // h_buf[0] + mbar init visible locally

    uint32_t hloc, mloc;
    asm("{ .reg .u64 t; cvta.to.shared.u64 t, %1; cvt.u32.u64 %0, t; }"
        : "=r"(hloc) : "l"(&h_buf[0][0]));
    asm("{ .reg .u64 t; cvta.to.shared.u64 t, %1; cvt.u32.u64 %0, t; }"
        : "=r"(mloc) : "l"(&mbar[0]));
    uint32_t hself, hpeer, mself, mpeer;
    asm("mapa.shared::cluster.u32 %0, %1, %2;" : "=r"(hself) : "r"(hloc), "r"(rank));
    asm("mapa.shared::cluster.u32 %0, %1, %2;" : "=r"(hpeer) : "r"(hloc), "r"(rank ^ 1));
    asm("mapa.shared::cluster.u32 %0, %1, %2;" : "=r"(mself) : "r"(mloc), "r"(rank));
    asm("mapa.shared::cluster.u32 %0, %1, %2;" : "=r"(mpeer) : "r"(mloc), "r"(rank ^ 1));

    const size_t zbase = (size_t)batch * S_LEN * H_DIM;

    float zc = 0.f, zn = 0.f;
    if (fin) zc = Z[zbase + gr];     // z(0) for this lane's row

    // Both CTAs' mbarriers initialized before any st.async targets them.
    asm volatile("barrier.cluster.arrive.aligned;" ::: "memory");
    asm volatile("barrier.cluster.wait.aligned;"   ::: "memory");

    // Arm phase 0 (mbar[0], parity 0): 1 arrival + 1024 tx bytes
    // (128 self stores * 4B + 128 peer stores * 4B).
    if (tid == 0)
        asm volatile("mbarrier.arrive.expect_tx.shared.b64 _, [%0], 1024;"
                     :: "r"(mloc) : "memory");

    int cur = 0;
    for (int t = 0; t < S_LEN; t++) {
        const int nxt = (cur == 2) ? 0 : cur + 1;

        // Prefetch z(t+1) (fully hidden under FMA + wait).
        if (fin && t + 1 < S_LEN)
            zn = Z[zbase + (size_t)(t + 1) * H_DIM + gr];

        // FMA phase: 4 accumulators (short dep chains), broadcast h loads.
        const ulonglong2* h8 =
            reinterpret_cast<const ulonglong2*>(h_buf[cur] + kq * 64);
        unsigned long long a0 = 0ULL, a1 = 0ULL, a2 = 0ULL, a3 = 0ULL;
#pragma unroll
        for (int j = 0; j < 4; j++) {
            ulonglong2 v0 = h8[4 * j + 0];
            ulonglong2 v1 = h8[4 * j + 1];
            ulonglong2 v2 = h8[4 * j + 2];
            ulonglong2 v3 = h8[4 * j + 3];
            fma2(a0, wp[8 * j + 0], v0.x);
            fma2(a0, wp[8 * j + 1], v0.y);
            fma2(a1, wp[8 * j + 2], v1.x);
            fma2(a1, wp[8 * j + 3], v1.y);
            fma2(a2, wp[8 * j + 4], v2.x);
            fma2(a2, wp[8 * j + 5], v2.y);
            fma2(a3, wp[8 * j + 6], v3.x);
            fma2(a3, wp[8 * j + 7], v3.y);
        }
        float2 u = unpack2(add2(add2(a0, a1), add2(a2, a3)));
        float s = u.x + u.y;
        // Cross-kq reduction inside the warp (lanes l, l^8, l^16, l^24).
        s += __shfl_xor_sync(0xffffffffu, s, 8);
        s += __shfl_xor_sync(0xffffffffu, s, 16);

        if (fin) {
            float hv = fast_tanh(s + zc);
            const uint32_t off = (uint32_t)((nxt * H_DIM + gr) * 4);
            asm volatile(
                "st.async.shared::cluster.mbarrier::complete_tx::bytes.b32 [%0], %1, [%2];"
                :: "r"(hpeer + off), "f"(hv),
                   "r"(mpeer + (uint32_t)((t & 1) * 8)) : "memory");
            asm volatile(
                "st.async.shared::cluster.mbarrier::complete_tx::bytes.b32 [%0], %1, [%2];"
                :: "r"(hself + off), "f"(hv),
                   "r"(mself + (uint32_t)((t & 1) * 8)) : "memory");
            Hout[zbase + (size_t)t * H_DIM + gr] = hv;
        }

        // Arm phase t+1 before waiting phase t (pre-arm completes are safe:
        // tx-count may go transiently negative; phase gated on the arrive).
        if (tid == 0 && t + 1 < S_LEN)
            asm volatile("mbarrier.arrive.expect_tx.shared.b64 _, [%0], 1024;"
                         :: "r"(mloc + (uint32_t)(((t + 1) & 1) * 8)) : "memory");

        // The ONLY per-step synchronization.
        mbar_wait(mloc + (uint32_t)((t & 1) * 8), (uint32_t)((t >> 1) & 1));

        zc = zn;
        cur = nxt;
    }

    // Our mbar phase S-1 completed => all st.async into our SMEM landed.
    // Cluster barrier: peer likewise done before either CTA exits.
    asm volatile("barrier.cluster.arrive.aligned;" ::: "memory");
    asm volatile("barrier.cluster.wait.aligned;"   ::: "memory");
}

// ---------------------------------------------------------------------------
extern "C" void kernel_launch(void* const* d_in, const int* in_sizes, int n_in,
                              void* d_out, int out_size)
{
    const float* x    = (const float*)d_in[0];
    const float* U0   = (const float*)d_in[1];
    const float* bU0  = (const float*)d_in[2];
    const float* W0   = (const float*)d_in[3];
    const float* bW0  = (const float*)d_in[4];
    const float* U1   = (const float*)d_in[5];
    const float* bU1  = (const float*)d_in[6];
    const float* W1   = (const float*)d_in[7];
    const float* bW1  = (const float*)d_in[8];
    const float* fc1W = (const float*)d_in[9];
    const float* fc1b = (const float*)d_in[10];
    const float* fc2W = (const float*)d_in[11];
    const float* fc2b = (const float*)d_in[12];
    const float* fc3W = (const float*)d_in[13];
    const float* fc3b = (const float*)d_in[14];
    float* out = (float*)d_out;

    float *bufA, *bufB, *bufC, *bufD, *M, *hW, *hb;
    cudaGetSymbolAddress((void**)&bufA, g_bufA);
    cudaGetSymbolAddress((void**)&bufB, g_bufB);
    cudaGetSymbolAddress((void**)&bufC, g_bufC);
    cudaGetSymbolAddress((void**)&bufD, g_bufD);
    cudaGetSymbolAddress((void**)&M,    g_M);
    cudaGetSymbolAddress((void**)&hW,   g_hW);
    cudaGetSymbolAddress((void**)&hb,   g_hb);

    dim3 blk(256);
    dim3 g256(2, NROWS / 128);   // N = 256
    dim3 g64(1, NROWS / 128);    // N = 64

    // Head fusion precompute: W' = fc3W @ fc2W @ fc1W ; b' = fc3W(fc2W b1 + b2) + b3
    matmul_nn<<<H_DIM, H_DIM>>>(fc2W, fc1W, M);
    matmul_nn<<<O_DIM, H_DIM>>>(fc3W, M, hW);
    head_bias<<<1, H_DIM>>>(fc2W, fc1b, fc2b, fc3W, fc3b, hb);

    // 1) Z0 = x @ U0^T + bU0 + bW0
    sgemm_bias<<<g256, blk>>>(x, U0, bU0, bW0, bufA, NROWS, H_DIM, I_DIM);
    // 2) scan layer 0 -> H0  (128 CTAs = 64 clusters, 1 batch each)
    scan_rnn<<<128, 512>>>(bufA, W0, bufB);
    // 3) Z1 = H0 @ U1^T + bU1 + bW1
    sgemm_bias<<<g256, blk>>>(bufB, U1, bU1, bW1, bufC, NROWS, H_DIM, H_DIM);
    // 4) scan layer 1 -> H1
    scan_rnn<<<128, 512>>>(bufC, W1, bufD);
    // 5) fused head: out = H1 @ W'^T + b'
    sgemm_bias<<<g64, blk>>>(bufD, hW, hb, nullptr, out, NROWS, O_DIM, H_DIM);
}

// round 13
// speedup vs baseline: 1.4758x; 1.4758x over previous
#include <cuda_runtime.h>
#include <cuda_bf16.h>
#include <cstdint>

#define S_LEN 2048
#define B_SZ  64
#define I_DIM 128
#define H_DIM 256
#define O_DIM 64
#define NROWS (S_LEN * B_SZ)   // 131072 rows, n = b*S + s

// Scratch (static device arrays: allocation-free rule).
__device__ float g_bufA[(size_t)NROWS * H_DIM];
__device__ float g_bufB[(size_t)NROWS * H_DIM];
__device__ float g_bufC[(size_t)NROWS * H_DIM];
__device__ float g_bufD[(size_t)NROWS * H_DIM];
// Head-fusion scratch
__device__ float g_M[H_DIM * H_DIM];     // fc2W @ fc1W
__device__ float g_hW[O_DIM * H_DIM];    // fc3W @ g_M
__device__ float g_hb[O_DIM];            // fused bias

// ---- packed fp32x2 helpers (sm_100+) --------------------------------------
__device__ __forceinline__ void fma2(unsigned long long& d,
                                     unsigned long long a,
                                     unsigned long long b)
{
    asm("fma.rn.f32x2 %0, %1, %2, %0;" : "+l"(d) : "l"(a), "l"(b));
}
__device__ __forceinline__ unsigned long long splat2(float x)
{
    unsigned long long r;
    asm("mov.b64 %0, {%1, %1};" : "=l"(r) : "f"(x));
    return r;
}
__device__ __forceinline__ float2 unpack2(unsigned long long v)
{
    float2 r;
    asm("mov.b64 {%0, %1}, %2;" : "=f"(r.x), "=f"(r.y) : "l"(v));
    return r;
}
// Branchless fast tanh: 1 - 2/(exp(2x)+1). Saturates correctly at +-1.
__device__ __forceinline__ float fast_tanh(float x)
{
    float e = __expf(2.f * x);
    return 1.f - __fdividef(2.f, e + 1.f);
}
// mbarrier parity wait (acquire.cluster: orders peer st.async data)
__device__ __forceinline__ void mbar_wait(uint32_t addr, uint32_t parity)
{
    uint32_t done;
    asm volatile(
        "{\n\t.reg .pred p;\n\t"
        "mbarrier.try_wait.parity.acquire.cluster.shared::cta.b64 p, [%1], %2;\n\t"
        "selp.b32 %0, 1, 0, p;\n\t}"
        : "=r"(done) : "r"(addr), "r"(parity) : "memory");
    if (!done) {
        asm volatile(
            "{\n\t.reg .pred P1;\n\t"
            "WL_%=:\n\t"
            "mbarrier.try_wait.parity.acquire.cluster.shared::cta.b64 P1, [%0], %1, 0x989680;\n\t"
            "@P1 bra.uni WD_%=;\n\t"
            "bra.uni WL_%=;\n\t"
            "WD_%=:\n\t}"
            :: "r"(addr), "r"(parity) : "memory");
    }
}

// ---------------------------------------------------------------------------
// GEMM: C[M,N] = A[M,K] @ W[N,K]^T + b1[n] (+ b2[n])
// BM=128, BN=128, BK=16, TM=TN=8, 256 threads. fp32x2 packed accumulation.
// (At the fp32 issue roofline per R7-R12 profiles -- frozen.)
// ---------------------------------------------------------------------------
__global__ __launch_bounds__(256, 2) void sgemm_bias(
    const float* __restrict__ A, const float* __restrict__ W,
    const float* __restrict__ b1, const float* __restrict__ b2,
    float* __restrict__ C, int M, int N, int K)
{
    constexpr int BM = 128, BN = 128, BK = 16, TM = 8, TN = 8;
    __shared__ __align__(16) float As[BK][BM + 4];
    __shared__ __align__(16) float Ws[BK][BN + 4];

    const int tid = threadIdx.x;
    const int tx  = tid & 15;   // n sub-tile
    const int ty  = tid >> 4;   // m sub-tile
    const int m0  = blockIdx.y * BM;
    const int n0  = blockIdx.x * BN;

    unsigned long long acc2[TM / 2][TN];
#pragma unroll
    for (int p = 0; p < TM / 2; p++)
#pragma unroll
        for (int j = 0; j < TN; j++) acc2[p][j] = 0ULL;

    for (int k0 = 0; k0 < K; k0 += BK) {
#pragma unroll
        for (int l = 0; l < 2; l++) {
            int idx = tid + l * 256;
            int r = idx >> 2;
            int c = (idx & 3) << 2;
            float4 v = *reinterpret_cast<const float4*>(
                A + (size_t)(m0 + r) * K + k0 + c);
            As[c + 0][r] = v.x; As[c + 1][r] = v.y;
            As[c + 2][r] = v.z; As[c + 3][r] = v.w;
        }
#pragma unroll
        for (int l = 0; l < 2; l++) {
            int idx = tid + l * 256;
            int r = idx >> 2;
            int c = (idx & 3) << 2;
            float4 v = make_float4(0.f, 0.f, 0.f, 0.f);
            if (n0 + r < N)
                v = *reinterpret_cast<const float4*>(
                    W + (size_t)(n0 + r) * K + k0 + c);
            Ws[c + 0][r] = v.x; Ws[c + 1][r] = v.y;
            Ws[c + 2][r] = v.z; Ws[c + 3][r] = v.w;
        }
        __syncthreads();

#pragma unroll
        for (int k = 0; k < BK; k++) {
            ulonglong2 ra = *reinterpret_cast<const ulonglong2*>(&As[k][ty * TM]);
            ulonglong2 rb = *reinterpret_cast<const ulonglong2*>(&As[k][ty * TM + 4]);
            unsigned long long rm2[4] = { ra.x, ra.y, rb.x, rb.y };

            float4 n0v = *reinterpret_cast<const float4*>(&Ws[k][tx * TN]);
            float4 n1v = *reinterpret_cast<const float4*>(&Ws[k][tx * TN + 4]);
            unsigned long long rn2[TN];
            rn2[0] = splat2(n0v.x); rn2[1] = splat2(n0v.y);
            rn2[2] = splat2(n0v.z); rn2[3] = splat2(n0v.w);
            rn2[4] = splat2(n1v.x); rn2[5] = splat2(n1v.y);
            rn2[6] = splat2(n1v.z); rn2[7] = splat2(n1v.w);

#pragma unroll
            for (int p = 0; p < TM / 2; p++)
#pragma unroll
                for (int j = 0; j < TN; j++)
                    fma2(acc2[p][j], rm2[p], rn2[j]);
        }
        __syncthreads();
    }

    const int gn0 = n0 + tx * TN;
    if (gn0 < N) {
        float bias[TN];
#pragma unroll
        for (int j = 0; j < TN; j++) {
            int gn = gn0 + j;
            bias[j] = b1[gn] + (b2 ? b2[gn] : 0.f);
        }
#pragma unroll
        for (int p = 0; p < TM / 2; p++) {
            float r0[TN], r1[TN];
#pragma unroll
            for (int j = 0; j < TN; j++) {
                float2 u = unpack2(acc2[p][j]);
                r0[j] = u.x + bias[j];
                r1[j] = u.y + bias[j];
            }
            int gm = m0 + ty * TM + 2 * p;
            float4 o;
            o = make_float4(r0[0], r0[1], r0[2], r0[3]);
            *reinterpret_cast<float4*>(C + (size_t)gm * N + gn0) = o;
            o = make_float4(r0[4], r0[5], r0[6], r0[7]);
            *reinterpret_cast<float4*>(C + (size_t)gm * N + gn0 + 4) = o;
            o = make_float4(r1[0], r1[1], r1[2], r1[3]);
            *reinterpret_cast<float4*>(C + (size_t)(gm + 1) * N + gn0) = o;
            o = make_float4(r1[4], r1[5], r1[6], r1[7]);
            *reinterpret_cast<float4*>(C + (size_t)(gm + 1) * N + gn0 + 4) = o;
        }
    }
}

// ---------------------------------------------------------------------------
// Small NN matmul for head fusion: C[i,j] = sum_k A[i,k] * B[k,j]
// ---------------------------------------------------------------------------
__global__ __launch_bounds__(256) void matmul_nn(
    const float* __restrict__ A, const float* __restrict__ B,
    float* __restrict__ C)
{
    __shared__ float arow[H_DIM];
    const int i = blockIdx.x, j = threadIdx.x;
    arow[j] = A[i * H_DIM + j];
    __syncthreads();
    float s = 0.f;
#pragma unroll 8
    for (int k = 0; k < H_DIM; k++)
        s = fmaf(arow[k], B[(size_t)k * H_DIM + j], s);
    C[i * H_DIM + j] = s;
}

// Fused head bias: b' = F3 @ (F2 @ b1 + b2) + b3. One block, 256 threads.
__global__ __launch_bounds__(256) void head_bias(
    const float* __restrict__ F2, const float* __restrict__ b1,
    const float* __restrict__ b2, const float* __restrict__ F3,
    const float* __restrict__ b3, float* __restrict__ bout)
{
    __shared__ float bt[H_DIM];
    const int t = threadIdx.x;
    float s = b2[t];
    for (int k = 0; k < H_DIM; k++)
        s = fmaf(F2[(size_t)t * H_DIM + k], b1[k], s);
    bt[t] = s;
    __syncthreads();
    if (t < O_DIM) {
        float s2 = b3[t];
        for (int k = 0; k < H_DIM; k++)
            s2 = fmaf(F3[(size_t)t * H_DIM + k], bt[k], s2);
        bout[t] = s2;
    }
}

// ---------------------------------------------------------------------------
// Recurrent scan (R9 scaffold + tail cuts): H[t] = tanh(Z[t] + W @ H[t-1]).
// 2-CTA cluster per batch; W register-resident (fp32x2 pairs along k).
// Split-wait: early warps (local k-half) flow through STS + S1/S2; late warps
// (peer k-half) wait the peer's st.async bytes on ping-pong mbarriers.
// R13 deltas vs R9: (1) explicit pairwise tree-sum of the 8 stage partials
// (float stage[128][9] -- conflict-free); (2) mbar arm hoisted to loop top
// (safe: S1(t-1) orders every thread after the late warps consumed phase t-2
// of mbar[t&1]); (3) reducer ordering: LDS tree -> tanh -> st.async -> STS
// -> Hout STG last.
// ---------------------------------------------------------------------------
__global__ void __cluster_dims__(2, 1, 1) __launch_bounds__(512, 1)
scan_rnn(const float* __restrict__ Z, const float* __restrict__ Wr,
         float* __restrict__ Hout)
{
    __shared__ __align__(16) float h_buf[2][H_DIM];
    __shared__ float stage[128][9];           // stride 9 floats -> conflict-free
    __shared__ __align__(8) unsigned long long mbar[2];

    const int tid = threadIdx.x;
    uint32_t rank_u;
    asm("mov.u32 %0, %%cluster_ctarank;" : "=r"(rank_u));
    const int rank  = (int)rank_u;
    const int batch = blockIdx.x >> 1;
    const int kc = tid >> 6;        // 0..7 (warp-uniform -> broadcast LDS)
    const int ri = tid & 63;        // 0..63
    const int row0 = rank * 128 + ri;
    const int row1 = row0 + 64;
    // k-chunk [kc*32, kc*32+32): produced by CTA (kc>>2).
    const bool is_late = ((kc >> 2) != rank);

    // W chunk packed fp32x2 pairs along k: rows {row0,row1}, k in [kc*32,+32)
    unsigned long long w0p[16], w1p[16];
#pragma unroll
    for (int j = 0; j < 8; j++) {
        ulonglong2 a = *reinterpret_cast<const ulonglong2*>(
            Wr + (size_t)row0 * H_DIM + kc * 32 + j * 4);
        w0p[j * 2 + 0] = a.x; w0p[j * 2 + 1] = a.y;
        ulonglong2 b = *reinterpret_cast<const ulonglong2*>(
            Wr + (size_t)row1 * H_DIM + kc * 32 + j * 4);
        w1p[j * 2 + 0] = b.x; w1p[j * 2 + 1] = b.y;
    }

    if (tid < H_DIM) { h_buf[0][tid] = 0.f; h_buf[1][tid] = 0.f; }
    if (tid == 0) {
        uint32_t mb;
        asm("{ .reg .u64 t; cvta.to.shared.u64 t, %1; cvt.u32.u64 %0, t; }"
            : "=r"(mb) : "l"(&mbar[0]));
        asm volatile("mbarrier.init.shared.b64 [%0], 1;" :: "r"(mb) : "memory");
        asm volatile("mbarrier.init.shared.b64 [%0], 1;" :: "r"(mb + 8) : "memory");
    }
    __syncthreads();

    uint32_t hloc, mloc;
    asm("{ .reg .u64 t; cvta.to.shared.u64 t, %1; cvt.u32.u64 %0, t; }"
        : "=r"(hloc) : "l"(&h_buf[0][0]));
    asm("{ .reg .u64 t; cvta.to.shared.u64 t, %1; cvt.u32.u64 %0, t; }"
        : "=r"(mloc) : "l"(&mbar[0]));
    uint32_t hpeer, mpeer;
    asm("mapa.shared::cluster.u32 %0, %1, %2;" : "=r"(hpeer) : "r"(hloc), "r"(rank ^ 1));
    asm("mapa.shared::cluster.u32 %0, %1, %2;" : "=r"(mpeer) : "r"(mloc), "r"(rank ^ 1));

    const size_t zbase = (size_t)batch * S_LEN * H_DIM;

    float zc = 0.f, zn = 0.f;
    if (tid < 128) zc = Z[zbase + rank * 128 + tid];   // t = 0 prefetch

    // mbarriers live in both CTAs before any st.async targets them
    asm volatile("barrier.cluster.arrive.aligned;" ::: "memory");
    asm volatile("barrier.cluster.wait.aligned;"   ::: "memory");

    for (int t = 0; t < S_LEN; t++) {
        const int cur = t & 1;
        const int nxt = cur ^ 1;

        // Arm phase t at loop top (off the reducer tail). Safe: phase t-2 of
        // mbar[t&1] was consumed by late warps before FMA(t-1); S1(t-1)
        // orders every thread -- including tid0 -- after that point.
        if (tid == 0)
            asm volatile("mbarrier.arrive.expect_tx.shared.b64 _, [%0], 512;"
                         :: "r"(mloc + (uint32_t)((t & 1) * 8)) : "memory");

        // Prefetch next z early (max slack before it is consumed next step).
        if (tid < 128 && t + 1 < S_LEN)
            zn = Z[zbase + (size_t)(t + 1) * H_DIM + rank * 128 + tid];

        // Late warps: wait for peer's phase-(t-1) st.async bytes.
        // Early warps: their h chunk arrived via STS + S2 of step t-1.
        if (t > 0 && is_late)
            mbar_wait(mloc + (uint32_t)(((t - 1) & 1) * 8),
                      (uint32_t)(((t - 1) >> 1) & 1));

        // Partial dot products: packed fp32x2, warp-broadcast loads of h
        const ulonglong2* h8 =
            reinterpret_cast<const ulonglong2*>(h_buf[cur] + kc * 32);
        unsigned long long a0p = 0ULL, a1p = 0ULL;
#pragma unroll
        for (int j = 0; j < 8; j++) {
            ulonglong2 hv = h8[j];
            fma2(a0p, w0p[j * 2 + 0], hv.x);
            fma2(a0p, w0p[j * 2 + 1], hv.y);
            fma2(a1p, w1p[j * 2 + 0], hv.x);
            fma2(a1p, w1p[j * 2 + 1], hv.y);
        }
        float2 u0 = unpack2(a0p);
        float2 u1 = unpack2(a1p);
        stage[ri][kc]      = u0.x + u0.y;
        stage[ri + 64][kc] = u1.x + u1.y;
        __syncthreads();                       // S1: all partials staged

        if (tid < 128) {
            // Pairwise tree (depth 3) instead of serial 8-chain.
            float q0 = stage[tid][0], q1 = stage[tid][1];
            float q2 = stage[tid][2], q3 = stage[tid][3];
            float q4 = stage[tid][4], q5 = stage[tid][5];
            float q6 = stage[tid][6], q7 = stage[tid][7];
            float s = (((q0 + q1) + (q2 + q3)) + ((q4 + q5) + (q6 + q7))) + zc;
            float hv = fast_tanh(s);
            const int gr = rank * 128 + tid;
            const uint32_t off = (uint32_t)((nxt * H_DIM + gr) * 4);
            // Peer copy first (start DSMEM transit ASAP), completes peer's mbar.
            asm volatile(
                "st.async.shared::cluster.mbarrier::complete_tx::bytes.b32 [%0], %1, [%2];"
                :: "r"(hpeer + off), "f"(hv),
                   "r"(mpeer + (uint32_t)((t & 1) * 8)) : "memory");
            // Local copy: plain smem store, ordered by S2.
            h_buf[nxt][gr] = hv;
            Hout[zbase + (size_t)t * H_DIM + gr] = hv;   // fire-and-forget
        }
        __syncthreads();                       // S2: local h visible to early warps
        zc = zn;
    }

    // Drain: last step's st.async must land before SMEM is torn down.
    mbar_wait(mloc + (uint32_t)(((S_LEN - 1) & 1) * 8),
              (uint32_t)(((S_LEN - 1) >> 1) & 1));
    asm volatile("barrier.cluster.arrive.aligned;" ::: "memory");
    asm volatile("barrier.cluster.wait.aligned;"   ::: "memory");
}

// ---------------------------------------------------------------------------
extern "C" void kernel_launch(void* const* d_in, const int* in_sizes, int n_in,
                              void* d_out, int out_size)
{
    const float* x    = (const float*)d_in[0];
    const float* U0   = (const float*)d_in[1];
    const float* bU0  = (const float*)d_in[2];
    const float* W0   = (const float*)d_in[3];
    const float* bW0  = (const float*)d_in[4];
    const float* U1   = (const float*)d_in[5];
    const float* bU1  = (const float*)d_in[6];
    const float* W1   = (const float*)d_in[7];
    const float* bW1  = (const float*)d_in[8];
    const float* fc1W = (const float*)d_in[9];
    const float* fc1b = (const float*)d_in[10];
    const float* fc2W = (const float*)d_in[11];
    const float* fc2b = (const float*)d_in[12];
    const float* fc3W = (const float*)d_in[13];
    const float* fc3b = (const float*)d_in[14];
    float* out = (float*)d_out;

    float *bufA, *bufB, *bufC, *bufD, *M, *hW, *hb;
    cudaGetSymbolAddress((void**)&bufA, g_bufA);
    cudaGetSymbolAddress((void**)&bufB, g_bufB);
    cudaGetSymbolAddress((void**)&bufC, g_bufC);
    cudaGetSymbolAddress((void**)&bufD, g_bufD);
    cudaGetSymbolAddress((void**)&M,    g_M);
    cudaGetSymbolAddress((void**)&hW,   g_hW);
    cudaGetSymbolAddress((void**)&hb,   g_hb);

    dim3 blk(256);
    dim3 g256(2, NROWS / 128);   // N = 256
    dim3 g64(1, NROWS / 128);    // N = 64

    // Head fusion precompute: W' = fc3W @ fc2W @ fc1W ; b' = fc3W(fc2W b1 + b2) + b3
    matmul_nn<<<H_DIM, H_DIM>>>(fc2W, fc1W, M);
    matmul_nn<<<O_DIM, H_DIM>>>(fc3W, M, hW);
    head_bias<<<1, H_DIM>>>(fc2W, fc1b, fc2b, fc3W, fc3b, hb);

    // 1) Z0 = x @ U0^T + bU0 + bW0
    sgemm_bias<<<g256, blk>>>(x, U0, bU0, bW0, bufA, NROWS, H_DIM, I_DIM);
    // 2) scan layer 0 -> H0  (128 CTAs = 64 clusters, 1 batch each)
    scan_rnn<<<128, 512>>>(bufA, W0, bufB);
    // 3) Z1 = H0 @ U1^T + bU1 + bW1
    sgemm_bias<<<g256, blk>>>(bufB, U1, bU1, bW1, bufC, NROWS, H_DIM, H_DIM);
    // 4) scan layer 1 -> H1
    scan_rnn<<<128, 512>>>(bufC, W1, bufD);
    // 5) fused head: out = H1 @ W'^T + b'
    sgemm_bias<<<g64, blk>>>(bufD, hW, hb, nullptr, out, NROWS, O_DIM, H_DIM);
}